// round 1
// baseline (speedup 1.0000x reference)
#include <cuda_runtime.h>
#include <cuda_fp16.h>
#include <cstdint>

#define N_NODES 8192
#define KDIM    256

// Persistent scratch (allocation-free rule: __device__ globals)
__device__ __half g_ah[(size_t)N_NODES * KDIM];        // A^T: [i][s], fp16, = wq[s]*f[s,i]
__device__ __half g_bh[(size_t)N_NODES * KDIM];        // B^T: [j][s], fp16, = wk[s]*f[s,j]
__device__ float  g_partial[64 * N_NODES];             // [jtile][i] masked row partial sums
__device__ float  g_rsum[N_NODES];                     // 1 / summed[i]

// ---------------------------------------------------------------------------
// Prep: transposed, scaled fp16 copies of f.  f is [s][i] (i contiguous);
// we want [i][s].  32x32 smem tile transpose.
// ---------------------------------------------------------------------------
__global__ void prep_kernel(const float* __restrict__ f,
                            const float* __restrict__ wq,
                            const float* __restrict__ wk) {
    __shared__ float tile[32][33];
    int ibase = blockIdx.x * 32;
    int sbase = blockIdx.y * 32;
    int tx = threadIdx.x, ty = threadIdx.y;   // (32, 8)
#pragma unroll
    for (int r = 0; r < 4; r++) {
        int s = sbase + ty + r * 8;
        tile[ty + r * 8][tx] = f[(size_t)s * N_NODES + ibase + tx];
    }
    __syncthreads();
    int s = sbase + tx;
    float q = wq[s], k = wk[s];
#pragma unroll
    for (int r = 0; r < 4; r++) {
        int i = ibase + ty + r * 8;
        float v = tile[tx][ty + r * 8];
        g_ah[(size_t)i * KDIM + s] = __float2half_rn(q * v);
        g_bh[(size_t)i * KDIM + s] = __float2half_rn(k * v);
    }
}

// ---------------------------------------------------------------------------
// cp.async helpers
// ---------------------------------------------------------------------------
__device__ __forceinline__ void cp_async16(void* smem, const void* gmem) {
    uint32_t s = (uint32_t)__cvta_generic_to_shared(smem);
    asm volatile("cp.async.cg.shared.global [%0], [%1], 16;\n" :: "r"(s), "l"(gmem));
}
__device__ __forceinline__ void cp_commit() {
    asm volatile("cp.async.commit_group;\n");
}
template <int N>
__device__ __forceinline__ void cp_wait() {
    asm volatile("cp.async.wait_group %0;\n" :: "n"(N));
}

__device__ __forceinline__ void mma16816(float c[4], const uint32_t a[4], const uint32_t b[2]) {
    asm volatile(
        "mma.sync.aligned.m16n8k16.row.col.f32.f16.f16.f32 "
        "{%0,%1,%2,%3}, {%4,%5,%6,%7}, {%8,%9}, {%0,%1,%2,%3};"
        : "+f"(c[0]), "+f"(c[1]), "+f"(c[2]), "+f"(c[3])
        : "r"(a[0]), "r"(a[1]), "r"(a[2]), "r"(a[3]), "r"(b[0]), "r"(b[1]));
}

// ---------------------------------------------------------------------------
// GEMM kernel: C tile 128x128, K=256 in 4 chunks of 64, double-buffered
// cp.async.  8 warps: 2 (M) x 4 (N), warp tile 64x32.
// PASS 1: masked exp row-sums -> g_partial.  PASS 2: out = exp(.)*rsum[j].
// ---------------------------------------------------------------------------
template <int PASS>
__global__ void __launch_bounds__(256)
gemm_kernel(const int* __restrict__ neighbors, float* __restrict__ out) {
    extern __shared__ __half smem[];
    constexpr int LD = 72;               // padded row stride (halfs) -> conflict-free
    constexpr int STG = 128 * LD;        // halfs per stage
    __half* As = smem;                   // [2][128][72]
    __half* Bs = smem + 2 * STG;         // [2][128][72]

    const int tid = threadIdx.x;
    const int lane = tid & 31;
    const int warp = tid >> 5;
    const int warp_m = warp & 1;         // 2 along M
    const int warp_n = warp >> 1;        // 4 along N
    const int bM = blockIdx.y * 128;
    const int bN = blockIdx.x * 128;

    const __half* gA = g_ah + (size_t)bM * KDIM;
    const __half* gB = g_bh + (size_t)bN * KDIM;

    float acc[4][4][4];
#pragma unroll
    for (int i = 0; i < 4; i++)
#pragma unroll
        for (int j = 0; j < 4; j++)
#pragma unroll
            for (int k = 0; k < 4; k++) acc[i][j][k] = 0.f;

    auto load_chunk = [&](int kc, int st) {
#pragma unroll
        for (int it = 0; it < 4; it++) {
            int idx = tid + it * 256;
            int row = idx >> 3, seg = idx & 7;
            cp_async16(&As[st * STG + row * LD + seg * 8], gA + (size_t)row * KDIM + kc * 64 + seg * 8);
        }
#pragma unroll
        for (int it = 0; it < 4; it++) {
            int idx = tid + it * 256;
            int row = idx >> 3, seg = idx & 7;
            cp_async16(&Bs[st * STG + row * LD + seg * 8], gB + (size_t)row * KDIM + kc * 64 + seg * 8);
        }
        cp_commit();
    };

    load_chunk(0, 0);

    const int r  = lane >> 2;
    const int cq = (lane & 3) * 2;

#pragma unroll
    for (int kc = 0; kc < 4; kc++) {
        if (kc + 1 < 4) { load_chunk(kc + 1, (kc + 1) & 1); cp_wait<1>(); }
        else            { cp_wait<0>(); }
        __syncthreads();
        const __half* A0 = &As[(kc & 1) * STG];
        const __half* B0 = &Bs[(kc & 1) * STG];
#pragma unroll
        for (int ks = 0; ks < 4; ks++) {
            uint32_t a[4][4], b[4][2];
#pragma unroll
            for (int mt = 0; mt < 4; mt++) {
                const __half* p = A0 + (warp_m * 64 + mt * 16 + r) * LD + ks * 16 + cq;
                a[mt][0] = *(const uint32_t*)p;
                a[mt][1] = *(const uint32_t*)(p + 8 * LD);
                a[mt][2] = *(const uint32_t*)(p + 8);
                a[mt][3] = *(const uint32_t*)(p + 8 * LD + 8);
            }
#pragma unroll
            for (int nt = 0; nt < 4; nt++) {
                const __half* p = B0 + (warp_n * 32 + nt * 8 + r) * LD + ks * 16 + cq;
                b[nt][0] = *(const uint32_t*)p;
                b[nt][1] = *(const uint32_t*)(p + 8);
            }
#pragma unroll
            for (int mt = 0; mt < 4; mt++)
#pragma unroll
                for (int nt = 0; nt < 4; nt++)
                    mma16816(acc[mt][nt], a[mt], b[nt]);
        }
        __syncthreads();
    }

    if (PASS == 1) {
        float rowsum[4][2];
#pragma unroll
        for (int mt = 0; mt < 4; mt++) { rowsum[mt][0] = 0.f; rowsum[mt][1] = 0.f; }
#pragma unroll
        for (int mt = 0; mt < 4; mt++)
#pragma unroll
            for (int nt = 0; nt < 4; nt++) {
                int gj  = bN + warp_n * 32 + nt * 8 + cq;
                int gi0 = bM + warp_m * 64 + mt * 16 + r;
                int2 m0 = *(const int2*)&neighbors[(size_t)gi0 * N_NODES + gj];
                int2 m1 = *(const int2*)&neighbors[(size_t)(gi0 + 8) * N_NODES + gj];
                const float* c = acc[mt][nt];
                rowsum[mt][0] += (m0.x ? __expf(c[0]) : 0.f) + (m0.y ? __expf(c[1]) : 0.f);
                rowsum[mt][1] += (m1.x ? __expf(c[2]) : 0.f) + (m1.y ? __expf(c[3]) : 0.f);
            }
        float* red = (float*)smem;       // [128][4], smem free after last sync
#pragma unroll
        for (int mt = 0; mt < 4; mt++)
#pragma unroll
            for (int h = 0; h < 2; h++) {
                float v = rowsum[mt][h];
                v += __shfl_xor_sync(0xffffffffu, v, 1);
                v += __shfl_xor_sync(0xffffffffu, v, 2);
                if ((lane & 3) == 0)
                    red[(warp_m * 64 + mt * 16 + r + h * 8) * 4 + warp_n] = v;
            }
        __syncthreads();
        if (tid < 128) {
            float s = red[tid * 4 + 0] + red[tid * 4 + 1] + red[tid * 4 + 2] + red[tid * 4 + 3];
            g_partial[(size_t)blockIdx.x * N_NODES + bM + tid] = s;
        }
    } else {
#pragma unroll
        for (int mt = 0; mt < 4; mt++)
#pragma unroll
            for (int nt = 0; nt < 4; nt++) {
                int gj  = bN + warp_n * 32 + nt * 8 + cq;
                int gi0 = bM + warp_m * 64 + mt * 16 + r;
                float r0 = g_rsum[gj], r1 = g_rsum[gj + 1];
                const float* c = acc[mt][nt];
                float2 v0 = make_float2(__expf(c[0]) * r0, __expf(c[1]) * r1);
                float2 v1 = make_float2(__expf(c[2]) * r0, __expf(c[3]) * r1);
                *(float2*)&out[(size_t)gi0 * N_NODES + gj]       = v0;
                *(float2*)&out[(size_t)(gi0 + 8) * N_NODES + gj] = v1;
            }
    }
}

// ---------------------------------------------------------------------------
// Reduce: summed[i] = sum over 64 jtiles of partials; store reciprocal.
// ---------------------------------------------------------------------------
__global__ void reduce_kernel() {
    int i = blockIdx.x * 256 + threadIdx.x;
    float s = 0.f;
#pragma unroll 8
    for (int jt = 0; jt < 64; jt++) s += g_partial[(size_t)jt * N_NODES + i];
    g_rsum[i] = 1.0f / s;
}

// ---------------------------------------------------------------------------
extern "C" void kernel_launch(void* const* d_in, const int* in_sizes, int n_in,
                              void* d_out, int out_size) {
    const float* f         = (const float*)d_in[0];
    const float* wq        = (const float*)d_in[1];
    const float* wk        = (const float*)d_in[2];
    const int*   neighbors = (const int*)d_in[3];
    float*       out       = (float*)d_out;

    const int smem_bytes = 4 * 128 * 72 * (int)sizeof(__half);   // 73728
    cudaFuncSetAttribute(gemm_kernel<1>, cudaFuncAttributeMaxDynamicSharedMemorySize, smem_bytes);
    cudaFuncSetAttribute(gemm_kernel<2>, cudaFuncAttributeMaxDynamicSharedMemorySize, smem_bytes);

    dim3 pgrid(N_NODES / 32, KDIM / 32);
    prep_kernel<<<pgrid, dim3(32, 8)>>>(f, wq, wk);

    dim3 ggrid(N_NODES / 128, N_NODES / 128);
    gemm_kernel<1><<<ggrid, 256, smem_bytes>>>(neighbors, out);
    reduce_kernel<<<N_NODES / 256, 256>>>();
    gemm_kernel<2><<<ggrid, 256, smem_bytes>>>(neighbors, out);
}

// round 3
// speedup vs baseline: 1.2913x; 1.2913x over previous
#include <cuda_runtime.h>
#include <cuda_fp16.h>
#include <cstdint>

#define N_NODES 8192
#define KDIM    256
#define TM      128
#define TN      128

// Persistent scratch (allocation-free rule: __device__ globals)
__device__ __half g_ah[(size_t)N_NODES * KDIM];   // A^T: [i][s] = wq[s]*f[s,i]
__device__ __half g_bh[(size_t)N_NODES * KDIM];   // B^T: [j][s] = wk[s]*f[s,j]
__device__ float  g_partial[64 * N_NODES];        // [jtile][i] masked row partials
__device__ float  g_rsum[N_NODES];                // 1 / summed[i]

// ---------------------------------------------------------------------------
// helpers
// ---------------------------------------------------------------------------
__device__ __forceinline__ uint32_t smem_u32(const void* p) {
    uint32_t a;
    asm("{ .reg .u64 t; cvta.to.shared.u64 t, %1; cvt.u32.u64 %0, t; }" : "=r"(a) : "l"(p));
    return a;
}
__device__ __forceinline__ void cp_async16(uint32_t smem, const void* gmem) {
    asm volatile("cp.async.cg.shared.global [%0], [%1], 16;\n" :: "r"(smem), "l"(gmem));
}
__device__ __forceinline__ void cp_commit() { asm volatile("cp.async.commit_group;\n"); }
template <int N> __device__ __forceinline__ void cp_wait() {
    asm volatile("cp.async.wait_group %0;\n" :: "n"(N));
}
#define LDMATRIX_X4(r0, r1, r2, r3, addr) \
    asm volatile("ldmatrix.sync.aligned.m8n8.x4.shared.b16 {%0,%1,%2,%3}, [%4];" \
                 : "=r"(r0), "=r"(r1), "=r"(r2), "=r"(r3) : "r"(addr))

__device__ __forceinline__ void mma16816(float c[4], const uint32_t a[4],
                                         uint32_t b0, uint32_t b1) {
    asm volatile(
        "mma.sync.aligned.m16n8k16.row.col.f32.f16.f16.f32 "
        "{%0,%1,%2,%3}, {%4,%5,%6,%7}, {%8,%9}, {%0,%1,%2,%3};"
        : "+f"(c[0]), "+f"(c[1]), "+f"(c[2]), "+f"(c[3])
        : "r"(a[0]), "r"(a[1]), "r"(a[2]), "r"(a[3]), "r"(b0), "r"(b1));
}

// ---------------------------------------------------------------------------
// Prep: transposed, scaled fp16 copies of f. f is [s][i]; want [i][s].
// ---------------------------------------------------------------------------
__global__ void prep_kernel(const float* __restrict__ f,
                            const float* __restrict__ wq,
                            const float* __restrict__ wk) {
    __shared__ float tile[32][33];
    int ibase = blockIdx.x * 32;
    int sbase = blockIdx.y * 32;
    int tx = threadIdx.x, ty = threadIdx.y;   // (32, 8)
#pragma unroll
    for (int r = 0; r < 4; r++) {
        int s = sbase + ty + r * 8;
        tile[ty + r * 8][tx] = f[(size_t)s * N_NODES + ibase + tx];
    }
    __syncthreads();
    int s = sbase + tx;
    float q = wq[s], k = wk[s];
#pragma unroll
    for (int r = 0; r < 4; r++) {
        int i = ibase + ty + r * 8;
        float v = tile[tx][ty + r * 8];
        g_ah[(size_t)i * KDIM + s] = __float2half_rn(q * v);
        g_bh[(size_t)i * KDIM + s] = __float2half_rn(k * v);
    }
}

// ---------------------------------------------------------------------------
// GEMM+exp: C tile 128x128, K=256 in 4 chunks of 64 halfs (128B rows,
// XOR-16B swizzle, no padding). 8 warps: 2(M) x 4(N), warp tile 64x32.
// ldmatrix.x4 fragment loads. Epilogue: write exp(dot) into out, accumulate
// masked row-partials into g_partial. 2 CTAs/SM (regs<=128, smem 64KB).
// smem: [A0 16K][A1 16K][B0 16K][B1 16K] = 65536 B
// ---------------------------------------------------------------------------
#define A_STG 16384
#define B_OFF 32768
#define SMEM_TOTAL 65536

__global__ void __launch_bounds__(256, 2)
gemm_exp(const int* __restrict__ neighbors, float* __restrict__ out) {
    extern __shared__ char smem[];
    const uint32_t sb = smem_u32(smem);
    const int tid  = threadIdx.x;
    const int lane = tid & 31;
    const int warp = tid >> 5;
    const int warp_m = warp & 1;          // 2 along M
    const int warp_n = warp >> 1;         // 4 along N
    const int bM = blockIdx.y * TM;
    const int bN = blockIdx.x * TN;

    const __half* gA = g_ah + (size_t)bM * KDIM;
    const __half* gB = g_bh + (size_t)bN * KDIM;

    float acc[4][4][4];
#pragma unroll
    for (int i = 0; i < 4; i++)
#pragma unroll
        for (int j = 0; j < 4; j++)
#pragma unroll
            for (int k = 0; k < 4; k++) acc[i][j][k] = 0.f;

    // cp.async tile loader: 128 rows x 8 segs(16B) per operand, 4 iters each
    auto load_chunk = [&](int kc, int st) {
        const __half* gAc = gA + kc * 64;
        const __half* gBc = gB + kc * 64;
#pragma unroll
        for (int it = 0; it < 4; it++) {
            int idx = tid + it * 256;
            int row = idx >> 3, seg = idx & 7;
            uint32_t sw = (uint32_t)row * 128 + (uint32_t)((seg ^ (row & 7)) << 4);
            cp_async16(sb + st * A_STG + sw, gAc + (size_t)row * KDIM + seg * 8);
            cp_async16(sb + B_OFF + st * A_STG + sw, gBc + (size_t)row * KDIM + seg * 8);
        }
        cp_commit();
    };

    // ldmatrix lane addressing (constant per thread)
    const int aRow = warp_m * 64 + (lane & 15);  // + mt*16
    const int aHi  = lane >> 4;
    const int bRow = warp_n * 32 + (lane & 7) + ((lane >> 4) << 3);  // + p*16
    const int bHi  = (lane >> 3) & 1;

    auto compute = [&](int st) {
        const uint32_t Ab = sb + st * A_STG;
        const uint32_t Bb = sb + B_OFF + st * A_STG;
#pragma unroll
        for (int ks = 0; ks < 4; ks++) {
            uint32_t a[4][4], b[2][4];
#pragma unroll
            for (int mt = 0; mt < 4; mt++) {
                uint32_t addr = Ab + (uint32_t)(aRow + mt * 16) * 128
                              + (uint32_t)((((ks * 2 + aHi) ^ (aRow & 7))) << 4);
                LDMATRIX_X4(a[mt][0], a[mt][1], a[mt][2], a[mt][3], addr);
            }
#pragma unroll
            for (int p = 0; p < 2; p++) {
                uint32_t addr = Bb + (uint32_t)(bRow + p * 16) * 128
                              + (uint32_t)((((ks * 2 + bHi) ^ (bRow & 7))) << 4);
                LDMATRIX_X4(b[p][0], b[p][1], b[p][2], b[p][3], addr);
            }
#pragma unroll
            for (int mt = 0; mt < 4; mt++)
#pragma unroll
                for (int nt = 0; nt < 4; nt++)
                    mma16816(acc[mt][nt], a[mt], b[nt >> 1][(nt & 1) * 2],
                             b[nt >> 1][(nt & 1) * 2 + 1]);
        }
    };

    // 2-stage pipeline over 4 K-chunks
    load_chunk(0, 0);
    load_chunk(1, 1);
#pragma unroll
    for (int kc = 0; kc < 4; kc++) {
        if (kc + 2 < 4) { cp_wait<1>(); }
        else            { cp_wait<0>(); }
        __syncthreads();
        compute(kc & 1);
        __syncthreads();
        if (kc + 2 < 4) load_chunk(kc + 2, kc & 1);
    }

    // ---- epilogue: out = exp(dot); masked row partial sums
    const int r  = lane >> 2;
    const int cq = (lane & 3) * 2;

    float rowsum[4][2];
#pragma unroll
    for (int mt = 0; mt < 4; mt++) { rowsum[mt][0] = 0.f; rowsum[mt][1] = 0.f; }

#pragma unroll
    for (int mt = 0; mt < 4; mt++)
#pragma unroll
        for (int nt = 0; nt < 4; nt++) {
            int gj  = bN + warp_n * 32 + nt * 8 + cq;
            int gi0 = bM + warp_m * 64 + mt * 16 + r;
            int2 m0 = *(const int2*)&neighbors[(size_t)gi0 * N_NODES + gj];
            int2 m1 = *(const int2*)&neighbors[(size_t)(gi0 + 8) * N_NODES + gj];
            const float* c = acc[mt][nt];
            float e0 = __expf(c[0]), e1 = __expf(c[1]);
            float e2 = __expf(c[2]), e3 = __expf(c[3]);
            *(float2*)&out[(size_t)gi0 * N_NODES + gj]       = make_float2(e0, e1);
            *(float2*)&out[(size_t)(gi0 + 8) * N_NODES + gj] = make_float2(e2, e3);
            if (m0.x) rowsum[mt][0] += e0;
            if (m0.y) rowsum[mt][0] += e1;
            if (m1.x) rowsum[mt][1] += e2;
            if (m1.y) rowsum[mt][1] += e3;
        }

    float* red = (float*)smem;   // [128][4] floats; smem free after last sync
#pragma unroll
    for (int mt = 0; mt < 4; mt++)
#pragma unroll
        for (int h = 0; h < 2; h++) {
            float v = rowsum[mt][h];
            v += __shfl_xor_sync(0xffffffffu, v, 1);
            v += __shfl_xor_sync(0xffffffffu, v, 2);
            if ((lane & 3) == 0)
                red[(warp_m * 64 + mt * 16 + r + h * 8) * 4 + warp_n] = v;
        }
    __syncthreads();
    if (tid < 128) {
        float s = red[tid * 4 + 0] + red[tid * 4 + 1] + red[tid * 4 + 2] + red[tid * 4 + 3];
        g_partial[(size_t)blockIdx.x * N_NODES + bM + tid] = s;
    }
}

// ---------------------------------------------------------------------------
// Reduce: summed[i] = sum over 64 jtiles; store reciprocal.
// ---------------------------------------------------------------------------
__global__ void reduce_kernel() {
    int i = blockIdx.x * 256 + threadIdx.x;
    float s = 0.f;
#pragma unroll 8
    for (int jt = 0; jt < 64; jt++) s += g_partial[(size_t)jt * N_NODES + i];
    g_rsum[i] = 1.0f / s;
}

// ---------------------------------------------------------------------------
// Scale: out[i][j] *= rsum[j]  (pure bandwidth, float4)
// ---------------------------------------------------------------------------
__global__ void __launch_bounds__(256)
scale_kernel(float* __restrict__ out) {
    size_t idx = (size_t)blockIdx.x * 256 + threadIdx.x;   // float4 index
    float4 v = ((const float4*)out)[idx];
    int j = (int)(idx & (N_NODES / 4 - 1)) * 4;
    float4 rs = *(const float4*)&g_rsum[j];
    v.x *= rs.x; v.y *= rs.y; v.z *= rs.z; v.w *= rs.w;
    ((float4*)out)[idx] = v;
}

// ---------------------------------------------------------------------------
extern "C" void kernel_launch(void* const* d_in, const int* in_sizes, int n_in,
                              void* d_out, int out_size) {
    const float* f         = (const float*)d_in[0];
    const float* wq        = (const float*)d_in[1];
    const float* wk        = (const float*)d_in[2];
    const int*   neighbors = (const int*)d_in[3];
    float*       out       = (float*)d_out;

    cudaFuncSetAttribute(gemm_exp, cudaFuncAttributeMaxDynamicSharedMemorySize, SMEM_TOTAL);

    dim3 pgrid(N_NODES / 32, KDIM / 32);
    prep_kernel<<<pgrid, dim3(32, 8)>>>(f, wq, wk);

    dim3 ggrid(N_NODES / TN, N_NODES / TM);   // (64, 64)
    gemm_exp<<<ggrid, 256, SMEM_TOTAL>>>(neighbors, out);

    reduce_kernel<<<N_NODES / 256, 256>>>();

    int nblk = (N_NODES / 4) * N_NODES / 256;  // 65536
    scale_kernel<<<nblk, 256>>>(out);
}

// round 5
// speedup vs baseline: 1.5161x; 1.1740x over previous
#include <cuda_runtime.h>
#include <cuda_fp16.h>
#include <cstdint>

#define N_NODES 8192
#define KDIM    256
#define TM      128
#define TN      128

// Persistent scratch (allocation-free rule: __device__ globals)
__device__ __half g_ah[(size_t)N_NODES * KDIM];     // A^T: [i][s] = wq[s]*f[s,i]
__device__ __half g_bh[(size_t)N_NODES * KDIM];     // B^T: [j][s] = wk[s]*f[s,j]
__device__ __half g_sh[(size_t)N_NODES * N_NODES];  // exp(QK^T) fp16 scratch (128MB)
__device__ float  g_partial[64 * N_NODES];          // [jtile][i] masked row partials
__device__ float  g_rsum[N_NODES];                  // 1 / summed[i]

// ---------------------------------------------------------------------------
// helpers
// ---------------------------------------------------------------------------
__device__ __forceinline__ uint32_t smem_u32(const void* p) {
    uint32_t a;
    asm("{ .reg .u64 t; cvta.to.shared.u64 t, %1; cvt.u32.u64 %0, t; }" : "=r"(a) : "l"(p));
    return a;
}
__device__ __forceinline__ void cp_async16(uint32_t smem, const void* gmem) {
    asm volatile("cp.async.cg.shared.global [%0], [%1], 16;\n" :: "r"(smem), "l"(gmem));
}
__device__ __forceinline__ void cp_commit() { asm volatile("cp.async.commit_group;\n"); }
template <int N> __device__ __forceinline__ void cp_wait() {
    asm volatile("cp.async.wait_group %0;\n" :: "n"(N));
}
#define LDMATRIX_X4(r0, r1, r2, r3, addr) \
    asm volatile("ldmatrix.sync.aligned.m8n8.x4.shared.b16 {%0,%1,%2,%3}, [%4];" \
                 : "=r"(r0), "=r"(r1), "=r"(r2), "=r"(r3) : "r"(addr))

__device__ __forceinline__ void mma16816(float c[4], const uint32_t a[4],
                                         uint32_t b0, uint32_t b1) {
    asm volatile(
        "mma.sync.aligned.m16n8k16.row.col.f32.f16.f16.f32 "
        "{%0,%1,%2,%3}, {%4,%5,%6,%7}, {%8,%9}, {%0,%1,%2,%3};"
        : "+f"(c[0]), "+f"(c[1]), "+f"(c[2]), "+f"(c[3])
        : "r"(a[0]), "r"(a[1]), "r"(a[2]), "r"(a[3]), "r"(b0), "r"(b1));
}

// ---------------------------------------------------------------------------
// Prep: transposed, scaled fp16 copies of f. f is [s][i]; want [i][s].
// ---------------------------------------------------------------------------
__global__ void prep_kernel(const float* __restrict__ f,
                            const float* __restrict__ wq,
                            const float* __restrict__ wk) {
    __shared__ float tile[32][33];
    int ibase = blockIdx.x * 32;
    int sbase = blockIdx.y * 32;
    int tx = threadIdx.x, ty = threadIdx.y;   // (32, 8)
#pragma unroll
    for (int r = 0; r < 4; r++) {
        int s = sbase + ty + r * 8;
        tile[ty + r * 8][tx] = f[(size_t)s * N_NODES + ibase + tx];
    }
    __syncthreads();
    int s = sbase + tx;
    float q = wq[s], k = wk[s];
#pragma unroll
    for (int r = 0; r < 4; r++) {
        int i = ibase + ty + r * 8;
        float v = tile[tx][ty + r * 8];
        g_ah[(size_t)i * KDIM + s] = __float2half_rn(q * v);
        g_bh[(size_t)i * KDIM + s] = __float2half_rn(k * v);
    }
}

// ---------------------------------------------------------------------------
// GEMM+exp: C tile 128x128, K=256 in 4 chunks of 64 halfs (128B rows,
// XOR-16B swizzle). 3-stage cp.async pipeline, 1 barrier/iter.
// 8 warps: 2(M) x 4(N), warp tile 64x32, ldmatrix.x4.
// Epilogue: exp -> fp16 staged in smem -> coalesced store to g_sh;
// masked fp32 row-partials -> g_partial.  2 CTAs/SM.
// smem: 3 stages x [A 16K | B 16K] = 98304 B; epilogue reuses [0,36864).
// Chunk->stage map: chunk kc lives in stage (kc % 3).
// ---------------------------------------------------------------------------
#define STG_SZ 32768
#define SMEM_TOTAL 98304
#define EPAD 136   // fp16 staging row stride (halfs): conflict-free

__global__ void __launch_bounds__(256, 2)
gemm_exp(const int* __restrict__ neighbors) {
    extern __shared__ char smem[];
    const uint32_t sb = smem_u32(smem);
    const int tid  = threadIdx.x;
    const int lane = tid & 31;
    const int warp = tid >> 5;
    const int warp_m = warp & 1;          // 2 along M
    const int warp_n = warp >> 1;         // 4 along N
    const int bM = blockIdx.y * TM;
    const int bN = blockIdx.x * TN;

    const __half* gA = g_ah + (size_t)bM * KDIM;
    const __half* gB = g_bh + (size_t)bN * KDIM;

    float acc[4][4][4];
#pragma unroll
    for (int i = 0; i < 4; i++)
#pragma unroll
        for (int j = 0; j < 4; j++)
#pragma unroll
            for (int k = 0; k < 4; k++) acc[i][j][k] = 0.f;

    // one K-chunk = 128 rows x 64 halfs (128B) for each of A, B
    auto load_chunk = [&](int kc, int st) {
        const __half* gAc = gA + kc * 64;
        const __half* gBc = gB + kc * 64;
        uint32_t base = sb + (uint32_t)st * STG_SZ;
#pragma unroll
        for (int it = 0; it < 4; it++) {
            int idx = tid + it * 256;
            int row = idx >> 3, seg = idx & 7;
            uint32_t sw = (uint32_t)row * 128 + (uint32_t)((seg ^ (row & 7)) << 4);
            cp_async16(base + sw, gAc + (size_t)row * KDIM + seg * 8);
            cp_async16(base + 16384 + sw, gBc + (size_t)row * KDIM + seg * 8);
        }
        cp_commit();
    };

    // ldmatrix lane addressing (constant per thread)
    const int aRow = warp_m * 64 + (lane & 15);  // + mt*16
    const int aHi  = lane >> 4;
    const int bRow = warp_n * 32 + (lane & 7) + ((lane >> 4) << 3);  // + p*16
    const int bHi  = (lane >> 3) & 1;

    auto compute = [&](int st) {
        const uint32_t Ab = sb + (uint32_t)st * STG_SZ;
        const uint32_t Bb = Ab + 16384;
#pragma unroll
        for (int ks = 0; ks < 4; ks++) {
            uint32_t a[4][4], b[2][4];
#pragma unroll
            for (int mt = 0; mt < 4; mt++) {
                uint32_t addr = Ab + (uint32_t)(aRow + mt * 16) * 128
                              + (uint32_t)((((ks * 2 + aHi) ^ (aRow & 7))) << 4);
                LDMATRIX_X4(a[mt][0], a[mt][1], a[mt][2], a[mt][3], addr);
            }
#pragma unroll
            for (int p = 0; p < 2; p++) {
                uint32_t addr = Bb + (uint32_t)(bRow + p * 16) * 128
                              + (uint32_t)((((ks * 2 + bHi) ^ (bRow & 7))) << 4);
                LDMATRIX_X4(b[p][0], b[p][1], b[p][2], b[p][3], addr);
            }
#pragma unroll
            for (int mt = 0; mt < 4; mt++)
#pragma unroll
                for (int nt = 0; nt < 4; nt++)
                    mma16816(acc[mt][nt], a[mt], b[nt >> 1][(nt & 1) * 2],
                             b[nt >> 1][(nt & 1) * 2 + 1]);
        }
    };

    // 3-stage pipeline over 4 K-chunks, 1 barrier per iteration
    load_chunk(0, 0);
    load_chunk(1, 1);
#pragma unroll
    for (int kc = 0; kc < 4; kc++) {
        if (kc < 3) { cp_wait<1>(); } else { cp_wait<0>(); }
        __syncthreads();
        compute(kc % 3);                       // chunk kc lives in stage kc%3
        if (kc + 2 < 4) load_chunk(kc + 2, (kc + 2) % 3);
    }
    __syncthreads();   // K-loop smem free -> reuse for epilogue staging

    // ---- epilogue: exp -> fp16 staging (smem) + masked rowsums
    __half* stg = (__half*)smem;                 // [128][EPAD]
    float*  red = (float*)(smem + 2 * 128 * EPAD);  // [128][4]

    const int r  = lane >> 2;
    const int cq = (lane & 3) * 2;

    float rowsum[4][2];
#pragma unroll
    for (int mt = 0; mt < 4; mt++) { rowsum[mt][0] = 0.f; rowsum[mt][1] = 0.f; }

#pragma unroll
    for (int mt = 0; mt < 4; mt++)
#pragma unroll
        for (int nt = 0; nt < 4; nt++) {
            int cl  = warp_n * 32 + nt * 8 + cq;          // local col 0..127
            int rl0 = warp_m * 64 + mt * 16 + r;          // local row 0..127
            int gi0 = bM + rl0;
            int gj  = bN + cl;
            int2 m0 = *(const int2*)&neighbors[(size_t)gi0 * N_NODES + gj];
            int2 m1 = *(const int2*)&neighbors[(size_t)(gi0 + 8) * N_NODES + gj];
            const float* c = acc[mt][nt];
            float e0 = __expf(c[0]), e1 = __expf(c[1]);
            float e2 = __expf(c[2]), e3 = __expf(c[3]);
            *(__half2*)&stg[rl0 * EPAD + cl]       = __floats2half2_rn(e0, e1);
            *(__half2*)&stg[(rl0 + 8) * EPAD + cl] = __floats2half2_rn(e2, e3);
            if (m0.x) rowsum[mt][0] += e0;
            if (m0.y) rowsum[mt][0] += e1;
            if (m1.x) rowsum[mt][1] += e2;
            if (m1.y) rowsum[mt][1] += e3;
        }

#pragma unroll
    for (int mt = 0; mt < 4; mt++)
#pragma unroll
        for (int h = 0; h < 2; h++) {
            float v = rowsum[mt][h];
            v += __shfl_xor_sync(0xffffffffu, v, 1);
            v += __shfl_xor_sync(0xffffffffu, v, 2);
            if ((lane & 3) == 0)
                red[(warp_m * 64 + mt * 16 + r + h * 8) * 4 + warp_n] = v;
        }
    __syncthreads();

    // coalesced fp16 tile store: 128 rows x 256B; 16 chunks of 16B per row
#pragma unroll
    for (int it = 0; it < 8; it++) {
        int idx = it * 256 + tid;            // 0..2047
        int row = idx >> 4;                  // 0..127
        int chunk = idx & 15;                // 16B chunks (8 halfs)
        uint4 v = *(const uint4*)(stg + row * EPAD + chunk * 8);
        *(uint4*)(g_sh + (size_t)(bM + row) * N_NODES + bN + chunk * 8) = v;
    }
    if (tid < 128) {
        float s = red[tid * 4 + 0] + red[tid * 4 + 1] + red[tid * 4 + 2] + red[tid * 4 + 3];
        g_partial[(size_t)blockIdx.x * N_NODES + bM + tid] = s;
    }
}

// ---------------------------------------------------------------------------
// Reduce: summed[i] = sum over 64 jtiles; store reciprocal.
// ---------------------------------------------------------------------------
__global__ void reduce_kernel() {
    int i = blockIdx.x * 256 + threadIdx.x;
    float s = 0.f;
#pragma unroll 8
    for (int jt = 0; jt < 64; jt++) s += g_partial[(size_t)jt * N_NODES + i];
    g_rsum[i] = 1.0f / s;
}

// ---------------------------------------------------------------------------
// Scale: out[i][j] = g_sh[i][j] * rsum[j]   (read 16B fp16, write 32B fp32)
// ---------------------------------------------------------------------------
__global__ void __launch_bounds__(256)
scale_kernel(float* __restrict__ out) {
    size_t idx = (size_t)blockIdx.x * 256 + threadIdx.x;   // uint4 index (8 halfs)
    uint4 h = ((const uint4*)g_sh)[idx];
    int j = (int)(idx & (N_NODES / 8 - 1)) * 8;
    float4 ra = *(const float4*)&g_rsum[j];
    float4 rb = *(const float4*)&g_rsum[j + 4];
    float2 f0 = __half22float2(*(__half2*)&h.x);
    float2 f1 = __half22float2(*(__half2*)&h.y);
    float2 f2 = __half22float2(*(__half2*)&h.z);
    float2 f3 = __half22float2(*(__half2*)&h.w);
    float4 o0 = make_float4(f0.x * ra.x, f0.y * ra.y, f1.x * ra.z, f1.y * ra.w);
    float4 o1 = make_float4(f2.x * rb.x, f2.y * rb.y, f3.x * rb.z, f3.y * rb.w);
    ((float4*)out)[idx * 2]     = o0;
    ((float4*)out)[idx * 2 + 1] = o1;
}

// ---------------------------------------------------------------------------
extern "C" void kernel_launch(void* const* d_in, const int* in_sizes, int n_in,
                              void* d_out, int out_size) {
    const float* f         = (const float*)d_in[0];
    const float* wq        = (const float*)d_in[1];
    const float* wk        = (const float*)d_in[2];
    const int*   neighbors = (const int*)d_in[3];
    float*       out       = (float*)d_out;

    cudaFuncSetAttribute(gemm_exp, cudaFuncAttributeMaxDynamicSharedMemorySize, SMEM_TOTAL);

    dim3 pgrid(N_NODES / 32, KDIM / 32);
    prep_kernel<<<pgrid, dim3(32, 8)>>>(f, wq, wk);

    dim3 ggrid(N_NODES / TN, N_NODES / TM);   // (64, 64)
    gemm_exp<<<ggrid, 256, SMEM_TOTAL>>>(neighbors);

    reduce_kernel<<<N_NODES / 256, 256>>>();

    size_t nvec = (size_t)N_NODES * N_NODES / 8;   // uint4 count
    scale_kernel<<<(int)(nvec / 256), 256>>>(out);
}